// round 6
// baseline (speedup 1.0000x reference)
#include <cuda_runtime.h>

// StripePolynomial2d — GB300 sm_103a, round 6
//
// vs R5: inner math converted to packed f32x2 (fma.rn.f32x2/add.rn.f32x2),
// processing batches in pairs. Coefficient selection becomes an arithmetic
// blend c = fma2(mf2, D, A) with mf in {0,1} and a prebuilt per-segment
// diff table D = coef(s+1)-coef(s), replacing 9 scalar FSELs per iteration.
// ~26% fewer dynamic instructions, core flops at 2 per instruction.

#define NW 129
#define PLANE (512*512)

typedef unsigned long long u64;

__device__ __forceinline__ u64 pk(float a, float b) {
    u64 r;
    asm("mov.b64 %0, {%1, %2};" : "=l"(r) : "f"(a), "f"(b));
    return r;
}
__device__ __forceinline__ u64 ffma2(u64 a, u64 b, u64 c) {
    u64 d;
    asm("fma.rn.f32x2 %0, %1, %2, %3;" : "=l"(d) : "l"(a), "l"(b), "l"(c));
    return d;
}
__device__ __forceinline__ u64 fadd2(u64 a, u64 b) {
    u64 d;
    asm("add.rn.f32x2 %0, %1, %2;" : "=l"(d) : "l"(a), "l"(b));
    return d;
}
__device__ __forceinline__ void upk(u64 v, float& lo, float& hi) {
    asm("mov.b64 {%0, %1}, %2;" : "=f"(lo), "=f"(hi) : "l"(v));
}

// coefA[g][c][seg][o] : (a0,a1,a2,_) prescaled by 0.25
// coefD[g][c][seg][o] : coefA(seg+1) - coefA(seg)  (zero at seg=63)
__device__ float4 g_coefA[1728];
__device__ float4 g_coefD[1728];

__global__ void build_coef_kernel(const float* __restrict__ Wt)
{
    int e = blockIdx.x * 256 + threadIdx.x;
    if (e >= 1728) return;
    int o = e % 3;
    int s = (e / 3) & 63;
    int c = (e / 192) % 3;
    int g = e / 576;

    auto coef_at = [&](int seg, float& a0, float& a1, float& a2) {
        int k = 2 * seg;
        float w0, w1, w2;
        if (g == 0) {
            const float* p0 = Wt + ((0 * 3 + o) * 3 + c) * NW + k;
            const float* p1 = Wt + ((1 * 3 + o) * 3 + c) * NW + k;
            w0 = p0[0] + p1[0];
            w1 = p0[1] + p1[1];
            w2 = p0[2] + p1[2];
        } else {
            const float* p = Wt + (((g + 1) * 3 + o) * 3 + c) * NW + k;
            w0 = p[0]; w1 = p[1]; w2 = p[2];
        }
        a0 = 0.25f * w1;
        a1 = 0.25f * (0.5f * (w2 - w0));
        a2 = 0.25f * (0.5f * (w0 + w2) - w1);
    };

    float a0, a1, a2;
    coef_at(s, a0, a1, a2);
    g_coefA[e] = make_float4(a0, a1, a2, 0.0f);

    float d0 = 0.0f, d1 = 0.0f, d2 = 0.0f;
    if (s < 63) {
        float b0, b1, b2;
        coef_at(s + 1, b0, b1, b2);
        d0 = b0 - a0; d1 = b1 - a1; d2 = b2 - a2;
    }
    g_coefD[e] = make_float4(d0, d1, d2, 0.0f);
}

__global__ __launch_bounds__(256)
void stripe_poly_kernel(const float* __restrict__ x,
                        float* __restrict__ out)
{
    __shared__ float4 cA[1728];
    __shared__ float4 cD[1728];
    #pragma unroll
    for (int e = threadIdx.x; e < 1728; e += 256) {
        cA[e] = g_coefA[e];
        cD[e] = g_coefD[e];
    }
    __syncthreads();

    int pid = blockIdx.x * 256 + threadIdx.x;
    int w = pid >> 9;
    int h = pid & 511;

    // analytic stripe positions (fp64 mirrors reference float64 grid math)
    const double RATIO = 512.0 / 513.0;
    double pw = (double)w, ph = (double)h;
    float base[3];
    base[0] = (float)(((pw)              * RATIO / 511.0  - 0.5) * 512.0) * 0.125f + 32.0f;
    base[1] = (float)(((pw + ph)         * RATIO / 1022.0 - 0.5) * 512.0) * 0.125f + 32.0f;
    base[2] = (float)(((pw - ph + 511.0) * RATIO / 1022.0 - 0.5) * 512.0) * 0.125f + 32.0f;

    // per-stripe-group: cross when x >= 8*(1-fb) (exact); xl = 0.25x + (2fb-1) - 2m
    float X[3];
    u64 dd2g[3];
    int offg[3];
    #pragma unroll
    for (int g = 0; g < 3; g++) {
        float bb = base[g];
        float s0f = fminf(fmaxf(floorf(bb), 0.0f), 63.0f);
        float fbg = bb - s0f;                                // exact
        X[g] = (s0f < 63.0f) ? 8.0f * (1.0f - fbg) : 1e30f;  // last seg: never cross
        float d0g = 2.0f * fbg - 1.0f;
        dd2g[g] = pk(d0g, d0g);
        offg[g] = g * 576 + (int)s0f * 3;                    // float4 index
    }

    const u64 Q2 = pk(0.25f, 0.25f);
    const u64 N2 = pk(-2.0f, -2.0f);

    u64 acc2[4][3];
    #pragma unroll
    for (int p = 0; p < 4; p++)
        #pragma unroll
        for (int o = 0; o < 3; o++)
            acc2[p][o] = 0ULL;

    #pragma unroll
    for (int c = 0; c < 3; c++) {
        float xv[8];
        #pragma unroll
        for (int b = 0; b < 8; b++)
            xv[b] = __ldg(x + (b * 3 + c) * PLANE + pid);
        u64 xv2[4];
        #pragma unroll
        for (int p = 0; p < 4; p++)
            xv2[p] = pk(xv[2 * p], xv[2 * p + 1]);

        #pragma unroll
        for (int g = 0; g < 3; g++) {
            int off = offg[g] + c * 192;
            float Xg = X[g];
            u64 dd2 = dd2g[g];

            u64 mf2[4], xl2[4];
            #pragma unroll
            for (int p = 0; p < 4; p++) {
                float m0 = (xv[2 * p]     >= Xg) ? 1.0f : 0.0f;
                float m1 = (xv[2 * p + 1] >= Xg) ? 1.0f : 0.0f;
                mf2[p] = pk(m0, m1);
                u64 t  = ffma2(Q2, xv2[p], dd2);
                xl2[p] = ffma2(N2, mf2[p], t);
            }

            #pragma unroll
            for (int o = 0; o < 3; o++) {
                float4 A = cA[off + o];
                float4 D = cD[off + o];
                u64 A0 = pk(A.x, A.x), A1 = pk(A.y, A.y), A2 = pk(A.z, A.z);
                u64 D0 = pk(D.x, D.x), D1 = pk(D.y, D.y), D2 = pk(D.z, D.z);
                #pragma unroll
                for (int p = 0; p < 4; p++) {
                    u64 q0 = ffma2(mf2[p], D0, A0);
                    u64 q1 = ffma2(mf2[p], D1, A1);
                    u64 q2 = ffma2(mf2[p], D2, A2);
                    u64 t  = ffma2(q2, xl2[p], q1);
                    t      = ffma2(t, xl2[p], q0);
                    acc2[p][o] = fadd2(acc2[p][o], t);
                }
            }
        }
    }

    #pragma unroll
    for (int p = 0; p < 4; p++)
        #pragma unroll
        for (int o = 0; o < 3; o++) {
            float lo, hi;
            upk(acc2[p][o], lo, hi);
            out[((2 * p)     * 3 + o) * PLANE + pid] = lo;
            out[((2 * p + 1) * 3 + o) * PLANE + pid] = hi;
        }
}

extern "C" void kernel_launch(void* const* d_in, const int* in_sizes, int n_in,
                              void* d_out, int out_size)
{
    const float* x  = (const float*)d_in[0];
    const float* Wt = (const float*)d_in[1];
    if (n_in >= 2 && in_sizes[0] == 4644) {
        Wt = (const float*)d_in[0];
        x  = (const float*)d_in[1];
    }
    float* out = (float*)d_out;

    build_coef_kernel<<<7, 256>>>(Wt);
    stripe_poly_kernel<<<(512 * 512) / 256, 256>>>(x, out);
}

// round 9
// speedup vs baseline: 1.4815x; 1.4815x over previous
#include <cuda_runtime.h>

// StripePolynomial2d — GB300 sm_103a, round 7
//
// vs R6: per-thread fp64 prologue (stripe bases, floor/clamp, crossover X,
// xl offset d0, segment offset) replaced by precomputed lookup tables
// g_pre0[512] (index w) and g_pre1[1023] (index w+h and w-h+511, same
// formula). Build kernel does all fp64 once. Removes fp64 register-pair
// pressure (target: <=85 regs -> 3 CTAs/SM) and ~60 instr/thread.
// Core stays f32x2 blend (R6).

#define NW 129
#define PLANE (512*512)

typedef unsigned long long u64;

__device__ __forceinline__ u64 pk(float a, float b) {
    u64 r;
    asm("mov.b64 %0, {%1, %2};" : "=l"(r) : "f"(a), "f"(b));
    return r;
}
__device__ __forceinline__ u64 ffma2(u64 a, u64 b, u64 c) {
    u64 d;
    asm("fma.rn.f32x2 %0, %1, %2, %3;" : "=l"(d) : "l"(a), "l"(b), "l"(c));
    return d;
}
__device__ __forceinline__ u64 fadd2(u64 a, u64 b) {
    u64 d;
    asm("add.rn.f32x2 %0, %1, %2;" : "=l"(d) : "l"(a), "l"(b));
    return d;
}
__device__ __forceinline__ void upk(u64 v, float& lo, float& hi) {
    asm("mov.b64 {%0, %1}, %2;" : "=f"(lo), "=f"(hi) : "l"(v));
}

// coefA[g][c][seg][o] : (a0,a1,a2,_) prescaled by 0.25
// coefD[g][c][seg][o] : coefA(seg+1) - coefA(seg)  (zero at seg=63)
__device__ float4 g_coefA[1728];
__device__ float4 g_coefD[1728];
// prologue tables: (X, d0, int_bits(seg*3), 0)
__device__ float4 g_pre0[512];    // index w        (stripe group 0)
__device__ float4 g_pre1[1023];   // index w+h (g1) and w-h+511 (g2)

__global__ void build_kernel(const float* __restrict__ Wt)
{
    int e = blockIdx.x * 256 + threadIdx.x;

    if (e < 1728) {
        int o = e % 3;
        int s = (e / 3) & 63;
        int c = (e / 192) % 3;
        int g = e / 576;

        auto coef_at = [&](int seg, float& a0, float& a1, float& a2) {
            int k = 2 * seg;
            float w0, w1, w2;
            if (g == 0) {
                const float* p0 = Wt + ((0 * 3 + o) * 3 + c) * NW + k;
                const float* p1 = Wt + ((1 * 3 + o) * 3 + c) * NW + k;
                w0 = p0[0] + p1[0];
                w1 = p0[1] + p1[1];
                w2 = p0[2] + p1[2];
            } else {
                const float* p = Wt + (((g + 1) * 3 + o) * 3 + c) * NW + k;
                w0 = p[0]; w1 = p[1]; w2 = p[2];
            }
            a0 = 0.25f * w1;
            a1 = 0.25f * (0.5f * (w2 - w0));
            a2 = 0.25f * (0.5f * (w0 + w2) - w1);
        };

        float a0, a1, a2;
        coef_at(s, a0, a1, a2);
        g_coefA[e] = make_float4(a0, a1, a2, 0.0f);

        float d0 = 0.0f, d1 = 0.0f, d2 = 0.0f;
        if (s < 63) {
            float b0, b1, b2;
            coef_at(s + 1, b0, b1, b2);
            d0 = b0 - a0; d1 = b1 - a1; d2 = b2 - a2;
        }
        g_coefD[e] = make_float4(d0, d1, d2, 0.0f);
        return;
    }

    // prologue tables (fp64 done once here, mirrors reference float64 grid math)
    const double RATIO = 512.0 / 513.0;
    float bb;
    float4* dst;
    if (e < 1728 + 512) {
        int i = e - 1728;
        bb = (float)(((double)i * RATIO / 511.0 - 0.5) * 512.0) * 0.125f + 32.0f;
        dst = &g_pre0[i];
    } else if (e < 1728 + 512 + 1023) {
        int i = e - (1728 + 512);
        bb = (float)(((double)i * RATIO / 1022.0 - 0.5) * 512.0) * 0.125f + 32.0f;
        dst = &g_pre1[i];
    } else {
        return;
    }
    float s0f = fminf(fmaxf(floorf(bb), 0.0f), 63.0f);
    float fb  = bb - s0f;                                 // exact
    float X   = (s0f < 63.0f) ? 8.0f * (1.0f - fb) : 1e30f;
    float d0  = 2.0f * fb - 1.0f;
    int   s3  = (int)s0f * 3;
    *dst = make_float4(X, d0, __int_as_float(s3), 0.0f);
}

__global__ __launch_bounds__(256)
void stripe_poly_kernel(const float* __restrict__ x,
                        float* __restrict__ out)
{
    __shared__ float4 cA[1728];
    __shared__ float4 cD[1728];
    #pragma unroll
    for (int e = threadIdx.x; e < 1728; e += 256) {
        cA[e] = g_coefA[e];
        cD[e] = g_coefD[e];
    }
    __syncthreads();

    int pid = blockIdx.x * 256 + threadIdx.x;
    int w = pid >> 9;
    int h = pid & 511;

    // table-driven prologue
    float4 P0 = g_pre0[w];
    float4 P1 = g_pre1[w + h];
    float4 P2 = g_pre1[w - h + 511];

    float X[3];
    u64 dd2g[3];
    int offg[3];
    X[0] = P0.x; dd2g[0] = pk(P0.y, P0.y); offg[0] =       __float_as_int(P0.z);
    X[1] = P1.x; dd2g[1] = pk(P1.y, P1.y); offg[1] = 576 + __float_as_int(P1.z);
    X[2] = P2.x; dd2g[2] = pk(P2.y, P2.y); offg[2] = 1152 + __float_as_int(P2.z);

    const u64 Q2 = pk(0.25f, 0.25f);
    const u64 N2 = pk(-2.0f, -2.0f);

    u64 acc2[4][3];
    #pragma unroll
    for (int p = 0; p < 4; p++)
        #pragma unroll
        for (int o = 0; o < 3; o++)
            acc2[p][o] = 0ULL;

    #pragma unroll
    for (int c = 0; c < 3; c++) {
        float xv[8];
        #pragma unroll
        for (int b = 0; b < 8; b++)
            xv[b] = __ldg(x + (b * 3 + c) * PLANE + pid);
        u64 xv2[4];
        #pragma unroll
        for (int p = 0; p < 4; p++)
            xv2[p] = pk(xv[2 * p], xv[2 * p + 1]);

        #pragma unroll
        for (int g = 0; g < 3; g++) {
            int off = offg[g] + c * 192;
            float Xg = X[g];
            u64 dd2 = dd2g[g];

            u64 mf2[4], xl2[4];
            #pragma unroll
            for (int p = 0; p < 4; p++) {
                float m0 = (xv[2 * p]     >= Xg) ? 1.0f : 0.0f;
                float m1 = (xv[2 * p + 1] >= Xg) ? 1.0f : 0.0f;
                mf2[p] = pk(m0, m1);
                u64 t  = ffma2(Q2, xv2[p], dd2);
                xl2[p] = ffma2(N2, mf2[p], t);
            }

            #pragma unroll
            for (int o = 0; o < 3; o++) {
                float4 A = cA[off + o];
                float4 D = cD[off + o];
                u64 A0 = pk(A.x, A.x), A1 = pk(A.y, A.y), A2 = pk(A.z, A.z);
                u64 D0 = pk(D.x, D.x), D1 = pk(D.y, D.y), D2 = pk(D.z, D.z);
                #pragma unroll
                for (int p = 0; p < 4; p++) {
                    u64 q0 = ffma2(mf2[p], D0, A0);
                    u64 q1 = ffma2(mf2[p], D1, A1);
                    u64 q2 = ffma2(mf2[p], D2, A2);
                    u64 t  = ffma2(q2, xl2[p], q1);
                    t      = ffma2(t, xl2[p], q0);
                    acc2[p][o] = fadd2(acc2[p][o], t);
                }
            }
        }
    }

    #pragma unroll
    for (int p = 0; p < 4; p++)
        #pragma unroll
        for (int o = 0; o < 3; o++) {
            float lo, hi;
            upk(acc2[p][o], lo, hi);
            out[((2 * p)     * 3 + o) * PLANE + pid] = lo;
            out[((2 * p + 1) * 3 + o) * PLANE + pid] = hi;
        }
}

extern "C" void kernel_launch(void* const* d_in, const int* in_sizes, int n_in,
                              void* d_out, int out_size)
{
    const float* x  = (const float*)d_in[0];
    const float* Wt = (const float*)d_in[1];
    if (n_in >= 2 && in_sizes[0] == 4644) {
        Wt = (const float*)d_in[0];
        x  = (const float*)d_in[1];
    }
    float* out = (float*)d_out;

    build_kernel<<<13, 256>>>(Wt);     // 1728 coef + 512 + 1023 table entries
    stripe_poly_kernel<<<(512 * 512) / 256, 256>>>(x, out);
}